// round 5
// baseline (speedup 1.0000x reference)
#include <cuda_runtime.h>
#include <cstdint>

// Problem constants: B=8, S=4096, H=16, E=64, s=64
#define NB 8
#define NH 16
#define NE 64
#define STOT 4096

#define TWO_PI 6.283185307179586476925f

__device__ float g_M[NH * 64 * 64];    // per-head dense operator M[h][n][j]

// ---------------------------------------------------------------------------
// PTX helpers
// ---------------------------------------------------------------------------
__device__ __forceinline__ uint32_t s2u(const void* p) {
    return (uint32_t)__cvta_generic_to_shared(p);
}
__device__ __forceinline__ void mbar_init(uint32_t a, uint32_t cnt) {
    asm volatile("mbarrier.init.shared.b64 [%0], %1;" :: "r"(a), "r"(cnt) : "memory");
}
__device__ __forceinline__ void mbar_expect(uint32_t a, uint32_t bytes) {
    asm volatile("mbarrier.arrive.expect_tx.shared.b64 _, [%0], %1;"
                 :: "r"(a), "r"(bytes) : "memory");
}
__device__ __forceinline__ void mbar_wait(uint32_t a, uint32_t ph) {
    asm volatile(
        "{\n\t"
        ".reg .pred P;\n\t"
        "WL%=:\n\t"
        "mbarrier.try_wait.parity.acquire.cta.shared::cta.b64 P, [%0], %1, 0x989680;\n\t"
        "@P bra WD%=;\n\t"
        "bra WL%=;\n\t"
        "WD%=:\n\t"
        "}" :: "r"(a), "r"(ph) : "memory");
}
__device__ __forceinline__ void bulk_g2s(uint32_t dst, const void* src,
                                         uint32_t bytes, uint32_t mbar) {
    asm volatile(
        "cp.async.bulk.shared::cluster.global.mbarrier::complete_tx::bytes "
        "[%0], [%1], %2, [%3];"
        :: "r"(dst), "l"(src), "r"(bytes), "r"(mbar) : "memory");
}

// ---------------------------------------------------------------------------
// Setup: 128 blocks = 16 heads x 8 n-chunks, 256 threads.
//   M[n][j] = (1/126) sum_{k<64} c_k Re( Z[k] * conj(w127^{k(63+j)}) * w126^{kn} )
// Z-DFT parallelized over 256 threads; all mods are single conditional
// subtracts so every loop fully unrolls.
// ---------------------------------------------------------------------------
__global__ __launch_bounds__(256, 4)
void fftbias_setup(const float* __restrict__ w) {
    const int h = blockIdx.x >> 3;
    const int c = blockIdx.x & 7;          // n-chunk (8 rows)
    const int tid = threadIdx.x;

    __shared__ float2 root127[127];
    __shared__ float2 root126[126];
    __shared__ float2 Zpart[4][64];
    __shared__ float2 Zsh[64];
    __shared__ float  zsh[128];

    if (tid < 127) {
        float sv, cv;
        sincosf(TWO_PI * (float)tid / 127.0f, &sv, &cv);
        root127[tid] = make_float2(cv, sv);
        zsh[tid] = w[h * 127 + tid];
    }
    if (tid < 126) {
        float sv, cv;
        sincosf(TWO_PI * (float)tid / 126.0f, &sv, &cv);
        root126[tid] = make_float2(cv, sv);
    }
    __syncthreads();

    // Z[k] = sum_u zsh[u] * conj(w127^{ku}), parallel over 4 u-chunks
    {
        const int k  = tid & 63;
        const int uc = tid >> 6;           // 0..3
        const int u0 = uc * 32;
        int m = (k * u0) % 127;
        float zr = 0.f, zi = 0.f;
        #pragma unroll
        for (int s = 0; s < 32; ++s) {
            int u = u0 + s;
            if (u < 127) {
                float2 rt = root127[m];
                float zu = zsh[u];
                zr += zu * rt.x;
                zi -= zu * rt.y;
            }
            m += k; if (m >= 127) m -= 127;
        }
        Zpart[uc][k] = make_float2(zr, zi);
    }
    __syncthreads();
    if (tid < 64) {
        float2 a = Zpart[0][tid], b = Zpart[1][tid];
        float2 d = Zpart[2][tid], f = Zpart[3][tid];
        Zsh[tid] = make_float2(a.x + b.x + d.x + f.x, a.y + b.y + d.y + f.y);
    }
    __syncthreads();

    // 8 n-rows x 64 j; thread handles (n, j) and (n, j+32)
    const int nl = tid >> 5;               // 0..7
    const int jl = tid & 31;               // 0..31
    const int n  = c * 8 + nl;
    const int stepA = 63 + jl;             // < 127
    const int stepB = 63 + jl + 32;        // < 127
    int m1a = 0, m1b = 0, m2 = 0;
    float accA = 0.f, accB = 0.f;
    #pragma unroll 8
    for (int k = 0; k < 64; ++k) {
        float2 Zk = Zsh[k];
        float2 r2 = root126[m2];
        float ck = (k == 0 || k == 63) ? 1.0f : 2.0f;
        {
            float2 r1 = root127[m1a];
            float ar = Zk.x * r1.x + Zk.y * r1.y;
            float ai = Zk.y * r1.x - Zk.x * r1.y;
            accA += ck * (ar * r2.x - ai * r2.y);
        }
        {
            float2 r1 = root127[m1b];
            float ar = Zk.x * r1.x + Zk.y * r1.y;
            float ai = Zk.y * r1.x - Zk.x * r1.y;
            accB += ck * (ar * r2.x - ai * r2.y);
        }
        m1a += stepA; if (m1a >= 127) m1a -= 127;
        m1b += stepB; if (m1b >= 127) m1b -= 127;
        m2  += n;     if (m2  >= 126) m2  -= 126;
    }
    g_M[h * 4096 + n * 64 + jl]      = accA * (1.0f / 126.0f);
    g_M[h * 4096 + n * 64 + jl + 32] = accB * (1.0f / 126.0f);
}

// ---------------------------------------------------------------------------
// Main: 128 blocks = (b,h), 512 threads, ~210KB smem, TMA-bulk-fed 8-stage
// pipeline.  Phase 1 streams v[b,:,h,:] once -> v_s/u_s.  Phase 2 matvecs
// against smem M.  Phase 3 streaming float4 stores.  b==0 blocks also emit
// the z_pb output (zp = 64 * M . o_).
// ---------------------------------------------------------------------------
__global__ __launch_bounds__(512, 1)
void fftbias_main(const float* __restrict__ v,
                  const float* __restrict__ o_,
                  float* __restrict__ out,
                  float* __restrict__ out2) {
    const int b = blockIdx.x >> 4;
    const int h = blockIdx.x & 15;
    const int tid = threadIdx.x;
    const int e = tid & 63;
    const int g = tid >> 6;                // 0..7

    extern __shared__ float sm[];
    float* slab = sm;                      // 8 stages * 4096 = 32768 floats
    float* Msh  = sm + 32768;              // 4096
    float* vs   = sm + 36864;              // 64*65
    float* us   = sm + 41024;              // 64*65
    float* rvs  = sm + 45184;              // 64*64
    float* rus  = sm + 49280;              // 64*64
    float* osh  = sm + 53376;              // 64
    float* zp   = sm + 53440;              // 64
    // mbarriers: 8 stage + 1 for M
    unsigned long long* mb = (unsigned long long*)(sm + 53504);
    const uint32_t mbar0 = s2u(mb);
    const uint32_t mbarM = mbar0 + 8 * 8;

    const float* vb = v + ((size_t)b * STOT * NH + h) * NE;   // elem [t*1024+e]

    if (tid == 0) {
        #pragma unroll
        for (int s = 0; s < 9; ++s) mbar_init(mbar0 + s * 8, 1);
        asm volatile("fence.proxy.async.shared::cta;" ::: "memory");
    }
    if (tid < 64) osh[tid] = o_[tid];
    for (int idx = tid; idx < 64 * 65; idx += 512) us[idx] = 0.f;
    __syncthreads();

    if (tid == 0) {
        // M tile (contiguous 16KB)
        mbar_expect(mbarM, 16384);
        bulk_g2s(s2u(Msh), g_M + h * 4096, 16384, mbarM);
        // first 7 slabs
        for (int p = 0; p < 7; ++p) {
            uint32_t mbr = mbar0 + (p & 7) * 8;
            mbar_expect(mbr, 16384);
            uint32_t dst = s2u(slab + (p & 7) * 4096);
            const float* src = vb + (size_t)p * 64 * 1024;
            for (int j = 0; j < 64; ++j)
                bulk_g2s(dst + j * 256, src + (size_t)j * 1024, 256, mbr);
        }
    }

    // ---- Phase 1: streaming reduce -----------------------------------------
    float vacc[8];
    #pragma unroll
    for (int k = 0; k < 8; ++k) vacc[k] = 0.f;

    for (int i = 0; i < 64; ++i) {
        mbar_wait(mbar0 + (i & 7) * 8, (i >> 3) & 1);

        const float* sl = slab + (i & 7) * 4096;
        float up = 0.f;
        #pragma unroll
        for (int k = 0; k < 8; ++k) {
            float x = sl[(g + 8 * k) * 64 + e];
            vacc[k] += x;                  // v_s[e][g+8k] partial over i
            up += x;                       // u_s[e][i] partial over j-subset
        }
        atomicAdd(&us[e * 65 + i], up);    // conflict-free (stride 65)

        __syncthreads();                   // all reads of slab i done

        if (tid == 0 && i + 7 < 64) {
            int ip = i + 7;
            uint32_t mbr = mbar0 + (ip & 7) * 8;
            mbar_expect(mbr, 16384);
            uint32_t dst = s2u(slab + (ip & 7) * 4096);
            const float* src = vb + (size_t)ip * 64 * 1024;
            for (int j = 0; j < 64; ++j)
                bulk_g2s(dst + j * 256, src + (size_t)j * 1024, 256, mbr);
        }
    }

    #pragma unroll
    for (int k = 0; k < 8; ++k) vs[e * 65 + g + 8 * k] = vacc[k];
    mbar_wait(mbarM, 0);                   // M tile ready (long done)
    __syncthreads();

    // ---- Phase 2: dense 64x64 matvecs per e --------------------------------
    float rv[8], ru[8];
    #pragma unroll
    for (int k = 0; k < 8; ++k) { rv[k] = 0.f; ru[k] = 0.f; }

    for (int j = 0; j < 64; ++j) {
        float a  = vs[e * 65 + j];
        float bb = us[e * 65 + j];
        #pragma unroll
        for (int k = 0; k < 8; ++k) {
            float m = Msh[(g + 8 * k) * 64 + j];   // warp-broadcast
            rv[k] += m * a;
            ru[k] += m * bb;
        }
    }
    #pragma unroll
    for (int k = 0; k < 8; ++k) {
        int n = g + 8 * k;
        rvs[n * 64 + e] = rv[k];
        rus[n * 64 + e] = ru[k];
    }
    __syncthreads();

    // ---- Phase 3: streaming float4 output ----------------------------------
    const int q = tid & 15;                // float4 slot within e
    const int rg = tid >> 4;               // 0..31 row group
    float* ob = out + ((size_t)b * STOT * NH + h) * NE;
    #pragma unroll 4
    for (int r = 0; r < 128; ++r) {
        int t = r * 32 + rg;
        int i = t >> 6, j = t & 63;
        float4 a = *(const float4*)&rvs[j * 64 + q * 4];
        float4 c = *(const float4*)&rus[i * 64 + q * 4];
        float4 o4 = make_float4(a.x + c.x, a.y + c.y, a.z + c.z, a.w + c.w);
        __stcs((float4*)&ob[(size_t)t * 1024 + q * 4], o4);
    }

    // ---- z_pb (b==0 blocks only): zp[n] = 64 * sum_j M[n][j] o_[j] ---------
    if (b == 0) {
        if (tid < 64) {
            float acc = 0.f;
            #pragma unroll
            for (int j = 0; j < 64; ++j) acc += Msh[tid * 64 + j] * osh[j];
            zp[tid] = 64.0f * acc;
        }
        __syncthreads();
        for (int idx = tid; idx < 4096; idx += 512) {
            int i = idx >> 6, j = idx & 63;
            out2[(size_t)idx * 16 + h] = zp[j] + zp[i];
        }
    }
}

// ---------------------------------------------------------------------------
extern "C" void kernel_launch(void* const* d_in, const int* in_sizes, int n_in,
                              void* d_out, int out_size) {
    const float* v  = (const float*)d_in[0];   // (8,4096,16,64) f32
    const float* w  = (const float*)d_in[1];   // (1,16,127) f32
    const float* o_ = (const float*)d_in[2];   // (64,) f32
    float* out  = (float*)d_out;
    float* out2 = out + (size_t)NB * STOT * NH * NE;   // z_pb region

    // floats: 53504 + mbarriers(9*8B) -> bytes
    const int smem_main = 53504 * 4 + 128;     // 214144 B

    cudaFuncSetAttribute(fftbias_main,
                         cudaFuncAttributeMaxDynamicSharedMemorySize, smem_main);

    fftbias_setup<<<128, 256>>>(w);
    fftbias_main<<<NB * NH, 512, smem_main>>>(v, o_, out, out2);
}

// round 6
// speedup vs baseline: 1.9021x; 1.9021x over previous
#include <cuda_runtime.h>
#include <cuda.h>
#include <cstdint>
#include <cstring>

// Problem constants: B=8, S=4096, H=16, E=64, s=64
#define NB 8
#define NH 16
#define NE 64
#define STOT 4096

#define TWO_PI 6.283185307179586476925f

__device__ float g_M[NH * 64 * 64];    // per-head dense operator M[h][n][j]

// ---------------------------------------------------------------------------
// PTX helpers
// ---------------------------------------------------------------------------
__device__ __forceinline__ uint32_t s2u(const void* p) {
    return (uint32_t)__cvta_generic_to_shared(p);
}
__device__ __forceinline__ void mbar_init(uint32_t a, uint32_t cnt) {
    asm volatile("mbarrier.init.shared.b64 [%0], %1;" :: "r"(a), "r"(cnt) : "memory");
}
__device__ __forceinline__ void mbar_expect(uint32_t a, uint32_t bytes) {
    asm volatile("mbarrier.arrive.expect_tx.shared.b64 _, [%0], %1;"
                 :: "r"(a), "r"(bytes) : "memory");
}
__device__ __forceinline__ void mbar_wait(uint32_t a, uint32_t ph) {
    asm volatile(
        "{\n\t"
        ".reg .pred P;\n\t"
        "WL%=:\n\t"
        "mbarrier.try_wait.parity.acquire.cta.shared::cta.b64 P, [%0], %1, 0x989680;\n\t"
        "@P bra WD%=;\n\t"
        "bra WL%=;\n\t"
        "WD%=:\n\t"
        "}" :: "r"(a), "r"(ph) : "memory");
}
__device__ __forceinline__ void bulk_g2s(uint32_t dst, const void* src,
                                         uint32_t bytes, uint32_t mbar) {
    asm volatile(
        "cp.async.bulk.shared::cluster.global.mbarrier::complete_tx::bytes "
        "[%0], [%1], %2, [%3];"
        :: "r"(dst), "l"(src), "r"(bytes), "r"(mbar) : "memory");
}
__device__ __forceinline__ void tma3d(uint32_t dst, const CUtensorMap* tm,
                                      int c0, int c1, int c2, uint32_t mbar) {
    asm volatile(
        "cp.async.bulk.tensor.3d.shared::cta.global.tile.mbarrier::complete_tx::bytes "
        "[%0], [%1, {%2, %3, %4}], [%5];"
        :: "r"(dst), "l"(tm), "r"(c0), "r"(c1), "r"(c2), "r"(mbar) : "memory");
}

// ---------------------------------------------------------------------------
// Setup: 128 blocks = 16 heads x 8 n-chunks, 256 threads.  (~2us, unchanged)
//   M[n][j] = (1/126) sum_{k<64} c_k Re( Z[k] * conj(w127^{k(63+j)}) * w126^{kn} )
// ---------------------------------------------------------------------------
__global__ __launch_bounds__(256, 4)
void fftbias_setup(const float* __restrict__ w) {
    const int h = blockIdx.x >> 3;
    const int c = blockIdx.x & 7;
    const int tid = threadIdx.x;

    __shared__ float2 root127[127];
    __shared__ float2 root126[126];
    __shared__ float2 Zpart[4][64];
    __shared__ float2 Zsh[64];
    __shared__ float  zsh[128];

    if (tid < 127) {
        float sv, cv;
        sincosf(TWO_PI * (float)tid / 127.0f, &sv, &cv);
        root127[tid] = make_float2(cv, sv);
        zsh[tid] = w[h * 127 + tid];
    }
    if (tid < 126) {
        float sv, cv;
        sincosf(TWO_PI * (float)tid / 126.0f, &sv, &cv);
        root126[tid] = make_float2(cv, sv);
    }
    __syncthreads();

    {
        const int k  = tid & 63;
        const int uc = tid >> 6;
        const int u0 = uc * 32;
        int m = (k * u0) % 127;
        float zr = 0.f, zi = 0.f;
        #pragma unroll
        for (int s = 0; s < 32; ++s) {
            int u = u0 + s;
            if (u < 127) {
                float2 rt = root127[m];
                float zu = zsh[u];
                zr += zu * rt.x;
                zi -= zu * rt.y;
            }
            m += k; if (m >= 127) m -= 127;
        }
        Zpart[uc][k] = make_float2(zr, zi);
    }
    __syncthreads();
    if (tid < 64) {
        float2 a = Zpart[0][tid], b = Zpart[1][tid];
        float2 d = Zpart[2][tid], f = Zpart[3][tid];
        Zsh[tid] = make_float2(a.x + b.x + d.x + f.x, a.y + b.y + d.y + f.y);
    }
    __syncthreads();

    const int nl = tid >> 5;
    const int jl = tid & 31;
    const int n  = c * 8 + nl;
    const int stepA = 63 + jl;
    const int stepB = 63 + jl + 32;
    int m1a = 0, m1b = 0, m2 = 0;
    float accA = 0.f, accB = 0.f;
    #pragma unroll 8
    for (int k = 0; k < 64; ++k) {
        float2 Zk = Zsh[k];
        float2 r2 = root126[m2];
        float ck = (k == 0 || k == 63) ? 1.0f : 2.0f;
        {
            float2 r1 = root127[m1a];
            float ar = Zk.x * r1.x + Zk.y * r1.y;
            float ai = Zk.y * r1.x - Zk.x * r1.y;
            accA += ck * (ar * r2.x - ai * r2.y);
        }
        {
            float2 r1 = root127[m1b];
            float ar = Zk.x * r1.x + Zk.y * r1.y;
            float ai = Zk.y * r1.x - Zk.x * r1.y;
            accB += ck * (ar * r2.x - ai * r2.y);
        }
        m1a += stepA; if (m1a >= 127) m1a -= 127;
        m1b += stepB; if (m1b >= 127) m1b -= 127;
        m2  += n;     if (m2  >= 126) m2  -= 126;
    }
    g_M[h * 4096 + n * 64 + jl]      = accA * (1.0f / 126.0f);
    g_M[h * 4096 + n * 64 + jl + 32] = accB * (1.0f / 126.0f);
}

// ---------------------------------------------------------------------------
// Main: 256 blocks = (b,h,e-half), 512 threads, ~97KB smem -> 2 CTAs/SM.
// Phase 1: TMA-tensor-fed 8-stage ring (one 8KB strided-gather op per slab).
// Phase 2: dense 64x64 matvec against M (TMA'd into dead slab region).
// Phase 3: streaming float4 stores.  b==0,eh==0 blocks also emit z_pb.
// ---------------------------------------------------------------------------
__global__ __launch_bounds__(512, 2)
void fftbias_main(const __grid_constant__ CUtensorMap tmap,
                  const float* __restrict__ o_,
                  float* __restrict__ out,
                  float* __restrict__ out2) {
    const int bx = blockIdx.x;
    const int b  = bx >> 5;
    const int h  = (bx >> 1) & 15;
    const int eh = bx & 1;                 // e-half
    const int tid = threadIdx.x;
    const int e = tid & 31;                // local e (0..31)
    const int g = tid >> 5;                // 0..15

    extern __shared__ __align__(1024) float sm[];
    float* slab = sm;                      // 8 stages * 2048 = 16384 floats
    float* Msh  = sm;                      // alias: M lives in stages 0-1 in phase 2
    float* vs   = sm + 16384;              // 32*65
    float* us   = sm + 18464;              // 32*65
    float* rvs  = sm + 20544;              // 64*32
    float* rus  = sm + 22592;              // 64*32
    float* osh  = sm + 24640;              // 64
    float* zp   = sm + 24704;              // 64
    unsigned long long* mb = (unsigned long long*)(sm + 24768);  // 8 stage + 1 M
    const uint32_t mbar0 = s2u(mb);
    const uint32_t mbarM = mbar0 + 64;

    const int c0 = eh * 32;                // e offset
    const int rowbase = b * STOT;          // dim2 base

    if (tid == 0) {
        #pragma unroll
        for (int s = 0; s < 9; ++s) mbar_init(mbar0 + s * 8, 1);
        asm volatile("fence.proxy.async.shared::cta;" ::: "memory");
    }
    if (tid < 64) osh[tid] = o_[tid];
    for (int idx = tid; idx < 32 * 65; idx += 512) us[idx] = 0.f;
    __syncthreads();

    if (tid == 0) {
        #pragma unroll
        for (int p = 0; p < 7; ++p) {
            uint32_t mbr = mbar0 + p * 8;
            mbar_expect(mbr, 8192);
            tma3d(s2u(slab + p * 2048), &tmap, c0, h, rowbase + p * 64, mbr);
        }
    }

    // ---- Phase 1: streaming reduce -----------------------------------------
    float vacc[4];
    #pragma unroll
    for (int k = 0; k < 4; ++k) vacc[k] = 0.f;

    for (int i = 0; i < 64; ++i) {
        mbar_wait(mbar0 + (i & 7) * 8, (i >> 3) & 1);

        const float* sl = slab + (i & 7) * 2048;
        float up = 0.f;
        #pragma unroll
        for (int k = 0; k < 4; ++k) {
            float x = sl[(g + 16 * k) * 32 + e];
            vacc[k] += x;                  // v_s[e][g+16k] partial over i
            up += x;                       // u_s[e][i] partial over j-subset
        }
        atomicAdd(&us[e * 65 + i], up);    // conflict-free (stride 65)

        __syncthreads();                   // all reads of stage (i-1)&7 long done

        if (tid == 0 && i + 7 < 64) {
            int ip = i + 7;
            asm volatile("fence.proxy.async.shared::cta;" ::: "memory");
            uint32_t mbr = mbar0 + (ip & 7) * 8;
            mbar_expect(mbr, 8192);
            tma3d(s2u(slab + (ip & 7) * 2048), &tmap, c0, h, rowbase + ip * 64, mbr);
        }
    }

    // all slab reads done (sync at i=63) -> fetch M into stages 0-1
    if (tid == 0) {
        asm volatile("fence.proxy.async.shared::cta;" ::: "memory");
        mbar_expect(mbarM, 16384);
        bulk_g2s(s2u(Msh), g_M + h * 4096, 16384, mbarM);
    }
    #pragma unroll
    for (int k = 0; k < 4; ++k) vs[e * 65 + g + 16 * k] = vacc[k];
    __syncthreads();
    mbar_wait(mbarM, 0);

    // ---- Phase 2: dense 64x64 matvecs per local e --------------------------
    float rv[4], ru[4];
    #pragma unroll
    for (int k = 0; k < 4; ++k) { rv[k] = 0.f; ru[k] = 0.f; }

    for (int j = 0; j < 64; ++j) {
        float a  = vs[e * 65 + j];
        float bb = us[e * 65 + j];
        #pragma unroll
        for (int k = 0; k < 4; ++k) {
            float m = Msh[(g + 16 * k) * 64 + j];   // warp-broadcast
            rv[k] += m * a;
            ru[k] += m * bb;
        }
    }
    #pragma unroll
    for (int k = 0; k < 4; ++k) {
        int n = g + 16 * k;
        rvs[n * 32 + e] = rv[k];
        rus[n * 32 + e] = ru[k];
    }
    __syncthreads();

    // ---- Phase 3: streaming float4 output ----------------------------------
    const int q  = tid & 7;                // float4 slot within 32-e half
    const int rg = tid >> 3;               // 0..63 (j)
    float* ob = out + ((size_t)b * STOT * NH + h) * NE + c0;
    float4 a4 = *(const float4*)&rvs[rg * 32 + q * 4];   // j = rg, invariant
    #pragma unroll 4
    for (int r = 0; r < 64; ++r) {         // i = r
        float4 c4 = *(const float4*)&rus[r * 32 + q * 4];
        float4 o4 = make_float4(a4.x + c4.x, a4.y + c4.y, a4.z + c4.z, a4.w + c4.w);
        __stcs((float4*)&ob[((size_t)(r * 64 + rg)) * 1024 + q * 4], o4);
    }

    // ---- z_pb (b==0, eh==0 blocks): zp[n] = 64 * sum_j M[n][j] o_[j] -------
    if (b == 0 && eh == 0) {
        if (tid < 64) {
            float acc = 0.f;
            #pragma unroll
            for (int j = 0; j < 64; ++j) acc += Msh[tid * 64 + j] * osh[j];
            zp[tid] = 64.0f * acc;
        }
        __syncthreads();
        for (int idx = tid; idx < 4096; idx += 512) {
            int i = idx >> 6, j = idx & 63;
            out2[(size_t)idx * 16 + h] = zp[j] + zp[i];
        }
    }
}

// ---------------------------------------------------------------------------
typedef CUresult (*PFN_tmapEncode)(CUtensorMap*, CUtensorMapDataType, cuuint32_t,
                                   void*, const cuuint64_t*, const cuuint64_t*,
                                   const cuuint32_t*, const cuuint32_t*,
                                   CUtensorMapInterleave, CUtensorMapSwizzle,
                                   CUtensorMapL2promotion, CUtensorMapFloatOOBfill);

extern "C" void kernel_launch(void* const* d_in, const int* in_sizes, int n_in,
                              void* d_out, int out_size) {
    const float* v  = (const float*)d_in[0];   // (8,4096,16,64) f32
    const float* w  = (const float*)d_in[1];   // (1,16,127) f32
    const float* o_ = (const float*)d_in[2];   // (64,) f32
    float* out  = (float*)d_out;
    float* out2 = out + (size_t)NB * STOT * NH * NE;   // z_pb region

    // Build the TMA descriptor (host, via cudart entry point -> no -lcuda)
    static CUtensorMap tmap;
    {
        PFN_tmapEncode encode = nullptr;
        cudaDriverEntryPointQueryResult qr;
        cudaGetDriverEntryPoint("cuTensorMapEncodeTiled", (void**)&encode,
                                cudaEnableDefault, &qr);
        cuuint64_t dims[3]    = {64, 16, (cuuint64_t)NB * STOT};
        cuuint64_t strides[2] = {256, 4096};          // bytes: h-stride, row-stride
        cuuint32_t box[3]     = {32, 1, 64};          // 8KB slab (e-half x 64 rows)
        cuuint32_t estr[3]    = {1, 1, 1};
        encode(&tmap, CU_TENSOR_MAP_DATA_TYPE_FLOAT32, 3, (void*)v,
               dims, strides, box, estr,
               CU_TENSOR_MAP_INTERLEAVE_NONE, CU_TENSOR_MAP_SWIZZLE_NONE,
               CU_TENSOR_MAP_L2_PROMOTION_L2_128B, CU_TENSOR_MAP_FLOAT_OOB_FILL_NONE);
    }

    const int smem_main = 24768 * 4 + 128;     // 99200 B (2 CTAs/SM)
    cudaFuncSetAttribute(fftbias_main,
                         cudaFuncAttributeMaxDynamicSharedMemorySize, smem_main);

    fftbias_setup<<<128, 256>>>(w);
    fftbias_main<<<NB * NH * 2, 512, smem_main>>>(tmap, o_, out, out2);
}

// round 7
// speedup vs baseline: 2.2912x; 1.2045x over previous
#include <cuda_runtime.h>
#include <cstdint>

// Problem constants: B=8, S=4096, H=16, E=64, s=64
#define NB 8
#define NH 16
#define NE 64
#define STOT 4096

#define TWO_PI 6.283185307179586476925f

__device__ float g_M[NH * 64 * 64];    // per-head dense operator M[h][n][j]

__device__ __forceinline__ void cp16(float* dst, const float* src) {
    uint32_t s = (uint32_t)__cvta_generic_to_shared(dst);
    asm volatile("cp.async.cg.shared.global [%0], [%1], 16;" :: "r"(s), "l"(src));
}

// ---------------------------------------------------------------------------
// Setup: 128 blocks = 16 heads x 8 n-chunks, 256 threads.  (~2us, unchanged)
//   M[n][j] = (1/126) sum_{k<64} c_k Re( Z[k] * conj(w127^{k(63+j)}) * w126^{kn} )
// ---------------------------------------------------------------------------
__global__ __launch_bounds__(256, 4)
void fftbias_setup(const float* __restrict__ w) {
    const int h = blockIdx.x >> 3;
    const int c = blockIdx.x & 7;
    const int tid = threadIdx.x;

    __shared__ float2 root127[127];
    __shared__ float2 root126[126];
    __shared__ float2 Zpart[4][64];
    __shared__ float2 Zsh[64];
    __shared__ float  zsh[128];

    if (tid < 127) {
        float sv, cv;
        sincosf(TWO_PI * (float)tid / 127.0f, &sv, &cv);
        root127[tid] = make_float2(cv, sv);
        zsh[tid] = w[h * 127 + tid];
    }
    if (tid < 126) {
        float sv, cv;
        sincosf(TWO_PI * (float)tid / 126.0f, &sv, &cv);
        root126[tid] = make_float2(cv, sv);
    }
    __syncthreads();

    {
        const int k  = tid & 63;
        const int uc = tid >> 6;
        const int u0 = uc * 32;
        int m = (k * u0) % 127;
        float zr = 0.f, zi = 0.f;
        #pragma unroll
        for (int s = 0; s < 32; ++s) {
            int u = u0 + s;
            if (u < 127) {
                float2 rt = root127[m];
                float zu = zsh[u];
                zr += zu * rt.x;
                zi -= zu * rt.y;
            }
            m += k; if (m >= 127) m -= 127;
        }
        Zpart[uc][k] = make_float2(zr, zi);
    }
    __syncthreads();
    if (tid < 64) {
        float2 a = Zpart[0][tid], b = Zpart[1][tid];
        float2 d = Zpart[2][tid], f = Zpart[3][tid];
        Zsh[tid] = make_float2(a.x + b.x + d.x + f.x, a.y + b.y + d.y + f.y);
    }
    __syncthreads();

    const int nl = tid >> 5;
    const int jl = tid & 31;
    const int n  = c * 8 + nl;
    const int stepA = 63 + jl;
    const int stepB = 63 + jl + 32;
    int m1a = 0, m1b = 0, m2 = 0;
    float accA = 0.f, accB = 0.f;
    #pragma unroll 8
    for (int k = 0; k < 64; ++k) {
        float2 Zk = Zsh[k];
        float2 r2 = root126[m2];
        float ck = (k == 0 || k == 63) ? 1.0f : 2.0f;
        {
            float2 r1 = root127[m1a];
            float ar = Zk.x * r1.x + Zk.y * r1.y;
            float ai = Zk.y * r1.x - Zk.x * r1.y;
            accA += ck * (ar * r2.x - ai * r2.y);
        }
        {
            float2 r1 = root127[m1b];
            float ar = Zk.x * r1.x + Zk.y * r1.y;
            float ai = Zk.y * r1.x - Zk.x * r1.y;
            accB += ck * (ar * r2.x - ai * r2.y);
        }
        m1a += stepA; if (m1a >= 127) m1a -= 127;
        m1b += stepB; if (m1b >= 127) m1b -= 127;
        m2  += n;     if (m2  >= 126) m2  -= 126;
    }
    g_M[h * 4096 + n * 64 + jl]      = accA * (1.0f / 126.0f);
    g_M[h * 4096 + n * 64 + jl + 32] = accB * (1.0f / 126.0f);
}

// ---------------------------------------------------------------------------
// Main: 256 blocks = (b,h,e-half), 512 threads, ~67KB smem (2 CTAs/SM).
// Phase 1: direct-LDG register-tile reduce — NO atomics, NO in-loop syncs.
//          Warp (jg,ig) + lane=e owns a 16i x 16j tile: vacc[16] / uacc[16]
//          in registers; 4-way cross-warp combine via padded smem partials.
// Phase 2: dense 64x64 matvec vs M (cp.async'd into dead partial region).
// Phase 3: streaming float4 stores.  b==0,eh==0 blocks also emit z_pb.
// ---------------------------------------------------------------------------
__global__ __launch_bounds__(512, 2)
void fftbias_main(const float* __restrict__ v,
                  const float* __restrict__ o_,
                  float* __restrict__ out,
                  float* __restrict__ out2) {
    const int bx = blockIdx.x;
    const int b  = bx >> 5;
    const int h  = (bx >> 1) & 15;
    const int eh = bx & 1;                 // e-half
    const int tid  = threadIdx.x;
    const int lane = tid & 31;             // local e (0..31)
    const int w    = tid >> 5;             // warp 0..15
    const int jg   = w & 3;                // j-group (16 j's)
    const int ig   = w >> 2;               // i-group (16 i's)

    extern __shared__ float sm[];
    float* vpart = sm;                     // [4][32][65] = 8320
    float* upart = sm + 8320;              // [4][32][65] = 8320
    // aliases (live after the reduction):
    float* vs  = vpart;                    // [32][65]  (== vpart[0], own-slot safe)
    float* rvs = vpart + 4160;             // [64][32]
    float* rus = vpart + 6208;             // [64][32]
    float* us  = upart;                    // [32][65]  (== upart[0])
    float* Msh = upart + 2080;             // [64][64]
    __shared__ float osh[64];
    __shared__ float zp[64];

    const float* vb = v + ((size_t)b * STOT * NH + h) * NE + eh * 32;

    if (tid < 64) osh[tid] = o_[tid];

    // ---- Phase 1: register-tile streaming reduce ---------------------------
    float vacc[16], uacc[16];
    #pragma unroll
    for (int k = 0; k < 16; ++k) { vacc[k] = 0.f; uacc[k] = 0.f; }

    const float* base = vb + lane;
    #pragma unroll
    for (int il = 0; il < 16; ++il) {
        const float* rowp =
            base + (size_t)((ig * 16 + il) * 64 + jg * 16) * 1024;
        #pragma unroll
        for (int jl = 0; jl < 16; ++jl) {
            float x = __ldcs(rowp + (size_t)jl * 1024);
            vacc[jl] += x;                 // v_s[e][jg*16+jl] partial (this ig)
            uacc[il] += x;                 // u_s[e][ig*16+il] partial (this jg)
        }
    }

    #pragma unroll
    for (int jl = 0; jl < 16; ++jl)
        vpart[(ig * 32 + lane) * 65 + jg * 16 + jl] = vacc[jl];
    #pragma unroll
    for (int il = 0; il < 16; ++il)
        upart[(jg * 32 + lane) * 65 + ig * 16 + il] = uacc[il];
    __syncthreads();

    // 4-way combine: each thread owns 4 (e,x) slots in each array
    #pragma unroll
    for (int k = 0; k < 4; ++k) {
        int s  = tid + k * 512;            // 0..2047
        int ee = s >> 6, xx = s & 63;
        int o65 = ee * 65 + xx;
        float a = vpart[o65] + vpart[2080 + o65] + vpart[4160 + o65] + vpart[6240 + o65];
        float c = upart[o65] + upart[2080 + o65] + upart[4160 + o65] + upart[6240 + o65];
        vs[o65] = a;                       // own slot (== vpart[0] copy)
        us[o65] = c;
    }
    __syncthreads();

    // fetch M_h into the now-dead upart tail
    {
        const float* Msrc = g_M + h * 4096;
        cp16(Msh + tid * 8,     Msrc + tid * 8);
        cp16(Msh + tid * 8 + 4, Msrc + tid * 8 + 4);
        asm volatile("cp.async.commit_group;");
        asm volatile("cp.async.wait_group 0;");
    }
    __syncthreads();

    // ---- Phase 2: dense 64x64 matvecs per local e --------------------------
    float rv[4], ru[4];
    #pragma unroll
    for (int k = 0; k < 4; ++k) { rv[k] = 0.f; ru[k] = 0.f; }

    for (int j = 0; j < 64; ++j) {
        float a  = vs[lane * 65 + j];
        float bb = us[lane * 65 + j];
        #pragma unroll
        for (int k = 0; k < 4; ++k) {
            float m = Msh[(w + 16 * k) * 64 + j];   // warp-broadcast
            rv[k] += m * a;
            ru[k] += m * bb;
        }
    }
    #pragma unroll
    for (int k = 0; k < 4; ++k) {
        int n = w + 16 * k;
        rvs[n * 32 + lane] = rv[k];
        rus[n * 32 + lane] = ru[k];
    }
    __syncthreads();

    // ---- Phase 3: streaming float4 output ----------------------------------
    const int q  = tid & 7;                // float4 slot within 32-e half
    const int rg = tid >> 3;               // 0..63 (j)
    float* ob = out + ((size_t)b * STOT * NH + h) * NE + eh * 32;
    float4 a4 = *(const float4*)&rvs[rg * 32 + q * 4];   // j = rg, invariant
    #pragma unroll 4
    for (int r = 0; r < 64; ++r) {         // i = r
        float4 c4 = *(const float4*)&rus[r * 32 + q * 4];
        float4 o4 = make_float4(a4.x + c4.x, a4.y + c4.y, a4.z + c4.z, a4.w + c4.w);
        __stcs((float4*)&ob[((size_t)(r * 64 + rg)) * 1024 + q * 4], o4);
    }

    // ---- z_pb (b==0, eh==0 blocks): zp[n] = 64 * sum_j M[n][j] o_[j] -------
    if (b == 0 && eh == 0) {
        if (tid < 64) {
            float acc = 0.f;
            #pragma unroll
            for (int j = 0; j < 64; ++j) acc += Msh[tid * 64 + j] * osh[j];
            zp[tid] = 64.0f * acc;
        }
        __syncthreads();
        for (int idx = tid; idx < 4096; idx += 512) {
            int i = idx >> 6, j = idx & 63;
            out2[(size_t)idx * 16 + h] = zp[j] + zp[i];
        }
    }
}

// ---------------------------------------------------------------------------
extern "C" void kernel_launch(void* const* d_in, const int* in_sizes, int n_in,
                              void* d_out, int out_size) {
    const float* v  = (const float*)d_in[0];   // (8,4096,16,64) f32
    const float* w  = (const float*)d_in[1];   // (1,16,127) f32
    const float* o_ = (const float*)d_in[2];   // (64,) f32
    float* out  = (float*)d_out;
    float* out2 = out + (size_t)NB * STOT * NH * NE;   // z_pb region

    const int smem_main = 16640 * 4;           // 66560 B -> 2 CTAs/SM

    cudaFuncSetAttribute(fftbias_main,
                         cudaFuncAttributeMaxDynamicSharedMemorySize, smem_main);

    fftbias_setup<<<128, 256>>>(w);
    fftbias_main<<<NB * NH * 2, 512, smem_main>>>(v, o_, out, out2);
}

// round 8
// speedup vs baseline: 2.3016x; 1.0046x over previous
#include <cuda_runtime.h>
#include <cstdint>

// Problem constants: B=8, S=4096, H=16, E=64, s=64
#define NB 8
#define NH 16
#define NE 64
#define STOT 4096

#define TWO_PI 6.283185307179586476925f

__device__ float g_M[NH * 64 * 64];    // per-head dense operator M[h][n][j]
__device__ int   g_ready[NH];          // monotone per-head chunk counter

__device__ __forceinline__ void cp16(float* dst, const float* src) {
    uint32_t s = (uint32_t)__cvta_generic_to_shared(dst);
    asm volatile("cp.async.cg.shared.global [%0], [%1], 16;" :: "r"(s), "l"(src));
}

// ---------------------------------------------------------------------------
// Single fused kernel: 256 blocks = (b,h,e-half), 512 threads, ~81KB dyn smem
// -> 2 CTAs/SM, all 256 CTAs co-resident (deadlock-free handshake).
//
// Builders (eh==0, one per (h, chunk=b)): compute 8 rows of M_h
//   M[n][j] = (1/126) sum_{k<64} c_k Re( Z[k] conj(w127^{k(63+j)}) w126^{kn} )
// publish to g_M, bump g_ready[h].  (~1-2us, runs before their phase 1.)
//
// Phase 1: direct-LDG register-tile reduce (no atomics, no in-loop syncs).
// Spin   : wait g_ready[h] >= 8 (free: phase 1 took ~25us).
// Phase 2: dense 64x64 matvec vs M (cp.async'd during the combine).
// Phase 3: streaming float4 stores.  b==0,eh==0 blocks also emit z_pb.
// ---------------------------------------------------------------------------
__global__ __launch_bounds__(512, 2)
void fftbias_fused(const float* __restrict__ v,
                   const float* __restrict__ w,
                   const float* __restrict__ o_,
                   float* __restrict__ out,
                   float* __restrict__ out2) {
    const int bx = blockIdx.x;
    const int b  = bx >> 5;
    const int h  = (bx >> 1) & 15;
    const int eh = bx & 1;                 // e-half
    const int tid  = threadIdx.x;
    const int lane = tid & 31;             // local e (0..31)
    const int wp   = tid >> 5;             // warp 0..15
    const int jg   = wp & 3;               // j-group (16 j's)
    const int ig   = wp >> 2;              // i-group (16 i's)

    extern __shared__ float sm[];
    float* vpart = sm;                     // [4][32][65] = 8320
    float* upart = sm + 8320;              // [4][32][65] = 8320
    float* Msh   = sm + 16640;             // [64][64]    = 4096 (dedicated)
    // aliases (live after the reduction):
    float* vs  = vpart;                    // [32][65]  (== vpart[0], own-slot safe)
    float* rvs = vpart + 4160;             // [64][32]
    float* rus = vpart + 6208;             // [64][32]
    float* us  = upart;                    // [32][65]  (== upart[0])
    __shared__ float osh[64];
    __shared__ float zp[64];

    if (tid < 64) osh[tid] = o_[tid];

    // ---- Builder prologue (eh==0 blocks): build chunk c=b of M_h -----------
    if (eh == 0) {
        const int c = b;                   // chunk index 0..7
        // scratch aliased into vpart (dead until phase-1 partial stores)
        float2* root127 = (float2*)vpart;          // 127
        float2* root126 = root127 + 128;           // 126
        float2* Zpart   = root126 + 128;           // 8*64
        float2* Zsh     = Zpart + 512;             // 64
        float*  zsh     = (float*)(Zsh + 64);      // 127

        if (tid < 127) {
            float sv, cv;
            sincosf(TWO_PI * (float)tid / 127.0f, &sv, &cv);
            root127[tid] = make_float2(cv, sv);
            zsh[tid] = w[h * 127 + tid];
        }
        if (tid < 126) {
            float sv, cv;
            sincosf(TWO_PI * (float)tid / 126.0f, &sv, &cv);
            root126[tid] = make_float2(cv, sv);
        }
        __syncthreads();

        // Z[k] = rfft_127(w_h)[k]: 8 u-chunks of 16 in parallel
        {
            const int k  = tid & 63;
            const int uc = tid >> 6;       // 0..7
            const int u0 = uc * 16;
            int m = (k * u0) % 127;
            float zr = 0.f, zi = 0.f;
            #pragma unroll
            for (int s = 0; s < 16; ++s) {
                int u = u0 + s;
                if (u < 127) {
                    float2 rt = root127[m];
                    float zu = zsh[u];
                    zr += zu * rt.x;
                    zi -= zu * rt.y;
                }
                m += k; if (m >= 127) m -= 127;
            }
            Zpart[uc * 64 + k] = make_float2(zr, zi);
        }
        __syncthreads();
        if (tid < 64) {
            float zr = 0.f, zi = 0.f;
            #pragma unroll
            for (int uc = 0; uc < 8; ++uc) {
                float2 p = Zpart[uc * 64 + tid];
                zr += p.x; zi += p.y;
            }
            Zsh[tid] = make_float2(zr, zi);
        }
        __syncthreads();

        // one M entry per thread: n = c*8 + (tid>>6), j = tid&63
        {
            const int nl = tid >> 6;
            const int j  = tid & 63;
            const int n  = c * 8 + nl;
            const int step1 = 63 + j;      // < 127
            int m1 = 0, m2 = 0;
            float acc = 0.f;
            #pragma unroll 8
            for (int k = 0; k < 64; ++k) {
                float2 Zk = Zsh[k];
                float2 r1 = root127[m1];
                float2 r2 = root126[m2];
                float ck = (k == 0 || k == 63) ? 1.0f : 2.0f;
                float ar = Zk.x * r1.x + Zk.y * r1.y;
                float ai = Zk.y * r1.x - Zk.x * r1.y;
                acc += ck * (ar * r2.x - ai * r2.y);
                m1 += step1; if (m1 >= 127) m1 -= 127;
                m2 += n;     if (m2 >= 126) m2 -= 126;
            }
            g_M[h * 4096 + n * 64 + j] = acc * (1.0f / 126.0f);
        }
        __syncthreads();                   // scratch dead; STGs issued
        if (tid == 0) {
            __threadfence();
            atomicAdd(&g_ready[h], 1);
        }
    }

    const float* vb = v + ((size_t)b * STOT * NH + h) * NE + eh * 32;

    // ---- Phase 1: register-tile streaming reduce ---------------------------
    float vacc[16], uacc[16];
    #pragma unroll
    for (int k = 0; k < 16; ++k) { vacc[k] = 0.f; uacc[k] = 0.f; }

    const float* base = vb + lane;
    #pragma unroll
    for (int il = 0; il < 16; ++il) {
        const float* rowp =
            base + (size_t)((ig * 16 + il) * 64 + jg * 16) * 1024;
        #pragma unroll
        for (int jl = 0; jl < 16; ++jl) {
            float x = __ldcs(rowp + (size_t)jl * 1024);
            vacc[jl] += x;                 // v_s[e][jg*16+jl] partial (this ig)
            uacc[il] += x;                 // u_s[e][ig*16+il] partial (this jg)
        }
    }

    #pragma unroll
    for (int jl = 0; jl < 16; ++jl)
        vpart[(ig * 32 + lane) * 65 + jg * 16 + jl] = vacc[jl];
    #pragma unroll
    for (int il = 0; il < 16; ++il)
        upart[(jg * 32 + lane) * 65 + ig * 16 + il] = uacc[il];
    __syncthreads();

    // ---- spin for M (published ~20us ago), then fetch during combine -------
    if (tid == 0) {
        while (*(volatile int*)&g_ready[h] < 8) {}
        __threadfence();                   // acquire
    }
    __syncthreads();

    {
        const float* Msrc = g_M + h * 4096;
        cp16(Msh + tid * 8,     Msrc + tid * 8);
        cp16(Msh + tid * 8 + 4, Msrc + tid * 8 + 4);
        asm volatile("cp.async.commit_group;");
    }

    // 4-way combine: each thread owns 4 (e,x) slots in each array
    #pragma unroll
    for (int k = 0; k < 4; ++k) {
        int s  = tid + k * 512;            // 0..2047
        int ee = s >> 6, xx = s & 63;
        int o65 = ee * 65 + xx;
        float a = vpart[o65] + vpart[2080 + o65] + vpart[4160 + o65] + vpart[6240 + o65];
        float c = upart[o65] + upart[2080 + o65] + upart[4160 + o65] + upart[6240 + o65];
        vs[o65] = a;                       // own slot (== vpart[0] copy)
        us[o65] = c;
    }
    asm volatile("cp.async.wait_group 0;");
    __syncthreads();

    // ---- Phase 2: dense 64x64 matvecs per local e --------------------------
    float rv[4], ru[4];
    #pragma unroll
    for (int k = 0; k < 4; ++k) { rv[k] = 0.f; ru[k] = 0.f; }

    for (int j = 0; j < 64; ++j) {
        float a  = vs[lane * 65 + j];
        float bb = us[lane * 65 + j];
        #pragma unroll
        for (int k = 0; k < 4; ++k) {
            float m = Msh[(wp + 16 * k) * 64 + j];  // warp-broadcast
            rv[k] += m * a;
            ru[k] += m * bb;
        }
    }
    #pragma unroll
    for (int k = 0; k < 4; ++k) {
        int n = wp + 16 * k;
        rvs[n * 32 + lane] = rv[k];
        rus[n * 32 + lane] = ru[k];
    }
    __syncthreads();

    // ---- Phase 3: streaming float4 output ----------------------------------
    const int q  = tid & 7;                // float4 slot within 32-e half
    const int rg = tid >> 3;               // 0..63 (j)
    float* ob = out + ((size_t)b * STOT * NH + h) * NE + eh * 32;
    float4 a4 = *(const float4*)&rvs[rg * 32 + q * 4];   // j = rg, invariant
    #pragma unroll 4
    for (int r = 0; r < 64; ++r) {         // i = r
        float4 c4 = *(const float4*)&rus[r * 32 + q * 4];
        float4 o4 = make_float4(a4.x + c4.x, a4.y + c4.y, a4.z + c4.z, a4.w + c4.w);
        __stcs((float4*)&ob[((size_t)(r * 64 + rg)) * 1024 + q * 4], o4);
    }

    // ---- z_pb (b==0, eh==0 blocks): zp[n] = 64 * sum_j M[n][j] o_[j] -------
    if (b == 0 && eh == 0) {
        if (tid < 64) {
            float acc = 0.f;
            #pragma unroll
            for (int j = 0; j < 64; ++j) acc += Msh[tid * 64 + j] * osh[j];
            zp[tid] = 64.0f * acc;
        }
        __syncthreads();
        for (int idx = tid; idx < 4096; idx += 512) {
            int i = idx >> 6, j = idx & 63;
            out2[(size_t)idx * 16 + h] = zp[j] + zp[i];
        }
    }
}

// ---------------------------------------------------------------------------
extern "C" void kernel_launch(void* const* d_in, const int* in_sizes, int n_in,
                              void* d_out, int out_size) {
    const float* v  = (const float*)d_in[0];   // (8,4096,16,64) f32
    const float* w  = (const float*)d_in[1];   // (1,16,127) f32
    const float* o_ = (const float*)d_in[2];   // (64,) f32
    float* out  = (float*)d_out;
    float* out2 = out + (size_t)NB * STOT * NH * NE;   // z_pb region

    const int smem_bytes = (8320 * 2 + 4096) * 4;      // 82944 B -> 2 CTAs/SM

    cudaFuncSetAttribute(fftbias_fused,
                         cudaFuncAttributeMaxDynamicSharedMemorySize, smem_bytes);

    fftbias_fused<<<NB * NH * 2, 512, smem_bytes>>>(v, w, o_, out, out2);
}

// round 9
// speedup vs baseline: 2.5450x; 1.1058x over previous
#include <cuda_runtime.h>
#include <cstdint>

// Problem constants: B=8, S=4096, H=16, E=64, s=64
#define NB 8
#define NH 16
#define NE 64
#define STOT 4096

#define TWO_PI 6.283185307179586476925f

__device__ float g_M[NH * 64 * 64];    // per-head dense operator M[h][n][j]
__device__ int   g_ready[NH];          // monotone per-head chunk counter (16 chunks)

__device__ __forceinline__ void cp16(float* dst, const float* src) {
    uint32_t s = (uint32_t)__cvta_generic_to_shared(dst);
    asm volatile("cp.async.cg.shared.global [%0], [%1], 16;" :: "r"(s), "l"(src));
}
__device__ __forceinline__ void pfL2(const float* p) {
    asm volatile("prefetch.global.L2 [%0];" :: "l"(p));
}

// ---------------------------------------------------------------------------
// Single fused kernel: 256 blocks = (b,h,e-half), 512 threads, ~81KB dyn smem
// -> 2 CTAs/SM, all 256 CTAs co-resident (deadlock-free handshake).
//
// Builders (ALL blocks, chunk = b*2+eh): compute 4 rows of M_h
//   M[n][j] = (1/126) sum_{k<64} c_k Re( Z[k] conj(w127^{k(63+j)}) w126^{kn} )
// with the k-loop split across thread pairs (~1us, equal on every CTA).
// L2 prefetch of the first quarter of phase-1 data is issued first so DRAM
// streams during the builder.
//
// Phase 1: direct-LDG register-tile reduce (no atomics, no in-loop syncs).
// Spin   : wait g_ready[h] >= 16 (free: phase 1 took ~25us).
// Phase 2: dense 64x64 matvec vs M (cp.async'd during the combine).
// Phase 3: streaming float4 stores.  b==0,eh==0 blocks also emit z_pb.
// ---------------------------------------------------------------------------
__global__ __launch_bounds__(512, 2)
void fftbias_fused(const float* __restrict__ v,
                   const float* __restrict__ w,
                   const float* __restrict__ o_,
                   float* __restrict__ out,
                   float* __restrict__ out2) {
    const int bx = blockIdx.x;
    const int b  = bx >> 5;
    const int h  = (bx >> 1) & 15;
    const int eh = bx & 1;                 // e-half
    const int tid  = threadIdx.x;
    const int lane = tid & 31;             // local e (0..31)
    const int wp   = tid >> 5;             // warp 0..15
    const int jg   = wp & 3;               // j-group (16 j's)
    const int ig   = wp >> 2;              // i-group (16 i's)

    extern __shared__ float sm[];
    float* vpart = sm;                     // [4][32][65] = 8320
    float* upart = sm + 8320;              // [4][32][65] = 8320
    float* Msh   = sm + 16640;             // [64][64]    = 4096 (dedicated)
    // aliases (live after the reduction):
    float* vs  = vpart;                    // [32][65]  (== vpart[0], own-slot safe)
    float* rvs = vpart + 4160;             // [64][32]
    float* rus = vpart + 6208;             // [64][32]
    float* us  = upart;                    // [32][65]  (== upart[0])
    __shared__ float osh[64];
    __shared__ float zp[64];

    const float* vb = v + ((size_t)b * STOT * NH + h) * NE + eh * 32;
    const float* base = vb + lane;

    // ---- L2 prefetch: first 4 row-tiles of this thread's phase-1 slice -----
    #pragma unroll
    for (int il = 0; il < 4; ++il) {
        const float* rowp = base + (size_t)((ig * 16 + il) * 64 + jg * 16) * 1024;
        #pragma unroll
        for (int jl = 0; jl < 16; ++jl) pfL2(rowp + (size_t)jl * 1024);
    }

    if (tid < 64) osh[tid] = o_[tid];

    // ---- Builder prologue (ALL blocks): build chunk c = b*2+eh of M_h ------
    {
        const int c = b * 2 + eh;          // chunk index 0..15 (4 n-rows each)
        // scratch aliased into vpart (dead until phase-1 partial stores)
        float2* root127 = (float2*)vpart;          // 128
        float2* root126 = root127 + 128;           // 128
        float2* Zpart   = root126 + 128;           // 8*64
        float2* Zsh     = Zpart + 512;             // 64
        float*  zsh     = (float*)(Zsh + 64);      // 127 (+pad)
        float*  part    = vpart + 2048;            // 512 partials

        if (tid < 127) {
            float sv, cv;
            sincosf(TWO_PI * (float)tid / 127.0f, &sv, &cv);
            root127[tid] = make_float2(cv, sv);
            zsh[tid] = w[h * 127 + tid];
        }
        if (tid < 126) {
            float sv, cv;
            sincosf(TWO_PI * (float)tid / 126.0f, &sv, &cv);
            root126[tid] = make_float2(cv, sv);
        }
        __syncthreads();

        // Z[k] = rfft_127(w_h)[k]: 8 u-chunks of 16 in parallel
        {
            const int k  = tid & 63;
            const int uc = tid >> 6;       // 0..7
            const int u0 = uc * 16;
            int m = (k * u0) % 127;
            float zr = 0.f, zi = 0.f;
            #pragma unroll
            for (int s = 0; s < 16; ++s) {
                int u = u0 + s;
                if (u < 127) {
                    float2 rt = root127[m];
                    float zu = zsh[u];
                    zr += zu * rt.x;
                    zi -= zu * rt.y;
                }
                m += k; if (m >= 127) m -= 127;
            }
            Zpart[uc * 64 + k] = make_float2(zr, zi);
        }
        __syncthreads();
        if (tid < 64) {
            float zr = 0.f, zi = 0.f;
            #pragma unroll
            for (int uc = 0; uc < 8; ++uc) {
                float2 p = Zpart[uc * 64 + tid];
                zr += p.x; zi += p.y;
            }
            Zsh[tid] = make_float2(zr, zi);
        }
        __syncthreads();

        // 4 rows x 64 j = 256 entries; k-loop halved across thread pairs
        {
            const int ent = tid & 255;
            const int kh  = tid >> 8;      // 0 or 1 (k-half)
            const int nl  = ent >> 6;      // 0..3
            const int j   = ent & 63;
            const int n   = c * 4 + nl;
            const int step1 = 63 + j;      // < 127
            int m1 = (kh * 32 * step1) % 127;
            int m2 = (kh * 32 * n) % 126;
            float acc = 0.f;
            #pragma unroll 8
            for (int kk = 0; kk < 32; ++kk) {
                const int k = kh * 32 + kk;
                float2 Zk = Zsh[k];
                float2 r1 = root127[m1];
                float2 r2 = root126[m2];
                float ck = (k == 0 || k == 63) ? 1.0f : 2.0f;
                float ar = Zk.x * r1.x + Zk.y * r1.y;
                float ai = Zk.y * r1.x - Zk.x * r1.y;
                acc += ck * (ar * r2.x - ai * r2.y);
                m1 += step1; if (m1 >= 127) m1 -= 127;
                m2 += n;     if (m2 >= 126) m2 -= 126;
            }
            part[tid] = acc;
        }
        __syncthreads();
        if (tid < 256) {
            const int nl = tid >> 6, j = tid & 63;
            const int n  = c * 4 + nl;
            g_M[h * 4096 + n * 64 + j] =
                (part[tid] + part[tid + 256]) * (1.0f / 126.0f);
        }
        __syncthreads();                   // scratch dead; STGs issued
        if (tid == 0) {
            __threadfence();
            atomicAdd(&g_ready[h], 1);
        }
    }

    // ---- Phase 1: register-tile streaming reduce ---------------------------
    float vacc[16], uacc[16];
    #pragma unroll
    for (int k = 0; k < 16; ++k) { vacc[k] = 0.f; uacc[k] = 0.f; }

    #pragma unroll
    for (int il = 0; il < 16; ++il) {
        const float* rowp =
            base + (size_t)((ig * 16 + il) * 64 + jg * 16) * 1024;
        #pragma unroll
        for (int jl = 0; jl < 16; ++jl) {
            float x = __ldcs(rowp + (size_t)jl * 1024);
            vacc[jl] += x;                 // v_s[e][jg*16+jl] partial (this ig)
            uacc[il] += x;                 // u_s[e][ig*16+il] partial (this jg)
        }
    }

    #pragma unroll
    for (int jl = 0; jl < 16; ++jl)
        vpart[(ig * 32 + lane) * 65 + jg * 16 + jl] = vacc[jl];
    #pragma unroll
    for (int il = 0; il < 16; ++il)
        upart[(jg * 32 + lane) * 65 + ig * 16 + il] = uacc[il];
    __syncthreads();

    // ---- spin for M (published ~20us ago), then fetch during combine -------
    if (tid == 0) {
        while (*(volatile int*)&g_ready[h] < 16) {}
        __threadfence();                   // acquire
    }
    __syncthreads();

    {
        const float* Msrc = g_M + h * 4096;
        cp16(Msh + tid * 8,     Msrc + tid * 8);
        cp16(Msh + tid * 8 + 4, Msrc + tid * 8 + 4);
        asm volatile("cp.async.commit_group;");
    }

    // 4-way combine: each thread owns 4 (e,x) slots in each array
    #pragma unroll
    for (int k = 0; k < 4; ++k) {
        int s  = tid + k * 512;            // 0..2047
        int ee = s >> 6, xx = s & 63;
        int o65 = ee * 65 + xx;
        float a = vpart[o65] + vpart[2080 + o65] + vpart[4160 + o65] + vpart[6240 + o65];
        float c = upart[o65] + upart[2080 + o65] + upart[4160 + o65] + upart[6240 + o65];
        vs[o65] = a;                       // own slot (== vpart[0] copy)
        us[o65] = c;
    }
    asm volatile("cp.async.wait_group 0;");
    __syncthreads();

    // ---- Phase 2: dense 64x64 matvecs per local e --------------------------
    float rv[4], ru[4];
    #pragma unroll
    for (int k = 0; k < 4; ++k) { rv[k] = 0.f; ru[k] = 0.f; }

    for (int j = 0; j < 64; ++j) {
        float a  = vs[lane * 65 + j];
        float bb = us[lane * 65 + j];
        #pragma unroll
        for (int k = 0; k < 4; ++k) {
            float m = Msh[(wp + 16 * k) * 64 + j];  // warp-broadcast
            rv[k] += m * a;
            ru[k] += m * bb;
        }
    }
    #pragma unroll
    for (int k = 0; k < 4; ++k) {
        int n = wp + 16 * k;
        rvs[n * 32 + lane] = rv[k];
        rus[n * 32 + lane] = ru[k];
    }
    __syncthreads();

    // ---- Phase 3: streaming float4 output ----------------------------------
    const int q  = tid & 7;                // float4 slot within 32-e half
    const int rg = tid >> 3;               // 0..63 (j)
    float* ob = out + ((size_t)b * STOT * NH + h) * NE + eh * 32;
    float4 a4 = *(const float4*)&rvs[rg * 32 + q * 4];   // j = rg, invariant
    #pragma unroll 4
    for (int r = 0; r < 64; ++r) {         // i = r
        float4 c4 = *(const float4*)&rus[r * 32 + q * 4];
        float4 o4 = make_float4(a4.x + c4.x, a4.y + c4.y, a4.z + c4.z, a4.w + c4.w);
        __stcs((float4*)&ob[((size_t)(r * 64 + rg)) * 1024 + q * 4], o4);
    }

    // ---- z_pb (b==0, eh==0 blocks): zp[n] = 64 * sum_j M[n][j] o_[j] -------
    if (b == 0 && eh == 0) {
        if (tid < 64) {
            float acc = 0.f;
            #pragma unroll
            for (int j = 0; j < 64; ++j) acc += Msh[tid * 64 + j] * osh[j];
            zp[tid] = 64.0f * acc;
        }
        __syncthreads();
        for (int idx = tid; idx < 4096; idx += 512) {
            int i = idx >> 6, j = idx & 63;
            out2[(size_t)idx * 16 + h] = zp[j] + zp[i];
        }
    }
}

// ---------------------------------------------------------------------------
extern "C" void kernel_launch(void* const* d_in, const int* in_sizes, int n_in,
                              void* d_out, int out_size) {
    const float* v  = (const float*)d_in[0];   // (8,4096,16,64) f32
    const float* w  = (const float*)d_in[1];   // (1,16,127) f32
    const float* o_ = (const float*)d_in[2];   // (64,) f32
    float* out  = (float*)d_out;
    float* out2 = out + (size_t)NB * STOT * NH * NE;   // z_pb region

    const int smem_bytes = (8320 * 2 + 4096) * 4;      // 82944 B -> 2 CTAs/SM

    cudaFuncSetAttribute(fftbias_fused,
                         cudaFuncAttributeMaxDynamicSharedMemorySize, smem_bytes);

    fftbias_fused<<<NB * NH * 2, 512, smem_bytes>>>(v, w, o_, out, out2);
}